// round 2
// baseline (speedup 1.0000x reference)
#include <cuda_runtime.h>
#include <math.h>

// ----------------------- problem dims -----------------------
// B=64, S_SRC=128, T_TRG=64 -> TDEC=63, E=512, H=1024, 4H=4096, NL=2
// SOS=1, SCALE=sqrt(512)

// ----------------------- device scratch (no allocation) -----------------------
__device__ float g_srcemb[8192 * 512];    // [B*S, E]      16.8 MB
__device__ float g_decemb[4032 * 512];    // [B*63, E]      8.3 MB
__device__ float g_pre[8192 * 4096];      // pre-gates     134 MB (reused per layer)
__device__ float g_seqA[8192 * 1024];     // enc L0 out seq
__device__ float g_seqB[8192 * 1024];     // enc L1 out seq
__device__ float g_dseqA[4032 * 1024];    // dec L0 out seq
__device__ float g_dseqB[4032 * 1024];    // dec L1 out seq
__device__ float g_preds[4032 * 512];
__device__ float g_scores[4032 * 128];    // scores -> softmax in place
__device__ float g_cstate[2 * 64 * 1024]; // c for layer-chain 0 and 1
__device__ float g_zero[1024];            // zero h row (broadcast via stride 0)

// ----------------------- init -----------------------
__global__ void zero_init() {
    int i = blockIdx.x * 256 + threadIdx.x;     // grid 512*256 = 131072
    if (i < 2 * 64 * 1024) g_cstate[i] = 0.f;
    if (i < 1024) g_zero[i] = 0.f;
}

// ----------------------- embedding gathers -----------------------
__global__ void gather_src(const int* __restrict__ src, const float* __restrict__ tab,
                           float* __restrict__ out) {
    int row = blockIdx.x;                        // b*128+s, 8192 rows
    int tok = src[row];
    const float4* r = (const float4*)(tab + (long long)tok * 512);
    float4* o = (float4*)(out + (long long)row * 512);
    o[threadIdx.x] = r[threadIdx.x];             // 128 threads * float4 = 512 floats
}

__global__ void gather_dec(const int* __restrict__ trg, const float* __restrict__ tab,
                           float* __restrict__ out) {
    int row = blockIdx.x;                        // b*63+t, 4032 rows
    int b = row / 63, t = row % 63;
    int tok = (t == 0) ? 1 : trg[b * 64 + t];    // SOS=1 at t=0, else trg[b][t]
    const float4* r = (const float4*)(tab + (long long)tok * 512);
    float4* o = (float4*)(out + (long long)row * 512);
    o[threadIdx.x] = r[threadIdx.x];
}

// ----------------------- generic C = alpha*(A @ W^T) + b1 + b2 -----------------------
// A:[M,K] rm, W:[N,K] rm, C:[M,N]. Tiles 128x64, BK=16, 256 thr, 8x4 microtile.
// Batched via blockIdx.z + strides. K must be a multiple of 16 (true here).
__global__ void __launch_bounds__(256) gemm_abt(
    const float* __restrict__ A, const float* __restrict__ W,
    const float* __restrict__ b1, const float* __restrict__ b2,
    float* __restrict__ C,
    int M, int N, int K, float alpha,
    long long strideA, long long strideW, long long strideC)
{
    A += (long long)blockIdx.z * strideA;
    W += (long long)blockIdx.z * strideW;
    C += (long long)blockIdx.z * strideC;

    __shared__ float As[16][132];
    __shared__ float Bs[16][68];

    int tid = threadIdx.x;
    int m0 = blockIdx.y * 128;
    int n0 = blockIdx.x * 64;
    int ty = tid >> 4, tx = tid & 15;

    float acc[8][4];
#pragma unroll
    for (int i = 0; i < 8; i++)
#pragma unroll
        for (int j = 0; j < 4; j++) acc[i][j] = 0.f;

    for (int kc = 0; kc < K; kc += 16) {
        // A tile: 128x16 = 512 float4, 2 per thread
#pragma unroll
        for (int r = 0; r < 2; r++) {
            int li = tid + r * 256;
            int m = li >> 2;
            int kq = li & 3;
            float4 v = {0.f, 0.f, 0.f, 0.f};
            if (m0 + m < M) v = *(const float4*)&A[(long long)(m0 + m) * K + kc + kq * 4];
            As[kq * 4 + 0][m] = v.x; As[kq * 4 + 1][m] = v.y;
            As[kq * 4 + 2][m] = v.z; As[kq * 4 + 3][m] = v.w;
        }
        // W tile: 64x16 = 256 float4, 1 per thread (N always multiple of 64 here)
        {
            int n = tid >> 2;
            int kq = tid & 3;
            float4 v = *(const float4*)&W[(long long)(n0 + n) * K + kc + kq * 4];
            Bs[kq * 4 + 0][n] = v.x; Bs[kq * 4 + 1][n] = v.y;
            Bs[kq * 4 + 2][n] = v.z; Bs[kq * 4 + 3][n] = v.w;
        }
        __syncthreads();
#pragma unroll
        for (int k = 0; k < 16; k++) {
            float a[8], w[4];
#pragma unroll
            for (int i = 0; i < 8; i++) a[i] = As[k][ty + 16 * i];
#pragma unroll
            for (int j = 0; j < 4; j++) w[j] = Bs[k][tx + 16 * j];
#pragma unroll
            for (int i = 0; i < 8; i++)
#pragma unroll
                for (int j = 0; j < 4; j++) acc[i][j] += a[i] * w[j];
        }
        __syncthreads();
    }
#pragma unroll
    for (int i = 0; i < 8; i++) {
        int m = m0 + ty + 16 * i;
        if (m >= M) continue;
#pragma unroll
        for (int j = 0; j < 4; j++) {
            int n = n0 + tx + 16 * j;
            float v = acc[i][j] * alpha;
            if (b1) v += b1[n];
            if (b2) v += b2[n];
            C[(long long)m * N + n] = v;
        }
    }
}

// ----------------------- fused LSTM timestep -----------------------
// gates[b, r] = pre[b*T+t, row(r)] + sum_k hprev[b,k] * Whh[row(r), k]
// Block: 128 blocks, block bx handles h-indices [bx*8, bx*8+8) for all 4 gates,
// all 64 batch rows. Epilogue applies LSTM cell and writes h into seq[t], c in place.
// hprev is read with per-batch stride hbstride (0 => broadcast zero row; or the
// previous timestep row of this layer's seq buffer; or encoder-final row for decoder t=0).
__global__ void __launch_bounds__(256) lstm_step(
    const float* __restrict__ pre,
    const float* __restrict__ Whh,
    const float* __restrict__ hprev, long long hbstride,
    float* __restrict__ cstate,
    float* __restrict__ seq,
    int t, int T)
{
    __shared__ float As[64][33];   // h chunk [b][k]
    __shared__ float Ws[32][33];   // Whh rows [r][k], r = g*8 + hl
    __shared__ float gs[64][33];   // gate partials [b][r]

    int tid = threadIdx.x;
    int hbase = blockIdx.x * 8;
    int ty = tid >> 4, tx = tid & 15;

    float a00 = 0.f, a01 = 0.f, a10 = 0.f, a11 = 0.f;
    float a20 = 0.f, a21 = 0.f, a30 = 0.f, a31 = 0.f;

    for (int kc = 0; kc < 1024; kc += 32) {
        // h chunk: 64x32 floats = 512 float4, 2 per thread
#pragma unroll
        for (int r = 0; r < 2; r++) {
            int li = tid + r * 256;
            int b = li >> 3;
            int kq = li & 7;
            float4 v = *(const float4*)&hprev[(long long)b * hbstride + kc + kq * 4];
            As[b][kq * 4 + 0] = v.x; As[b][kq * 4 + 1] = v.y;
            As[b][kq * 4 + 2] = v.z; As[b][kq * 4 + 3] = v.w;
        }
        // Whh chunk: 32 rows x 32 k = 256 float4, 1 per thread
        {
            int r = tid >> 3;
            int kq = tid & 7;
            int grow = (r >> 3) * 1024 + hbase + (r & 7);
            float4 v = *(const float4*)&Whh[(long long)grow * 1024 + kc + kq * 4];
            Ws[r][kq * 4 + 0] = v.x; Ws[r][kq * 4 + 1] = v.y;
            Ws[r][kq * 4 + 2] = v.z; Ws[r][kq * 4 + 3] = v.w;
        }
        __syncthreads();
#pragma unroll
        for (int k = 0; k < 32; k++) {
            float h0 = As[ty][k], h1 = As[ty + 16][k], h2 = As[ty + 32][k], h3 = As[ty + 48][k];
            float w0 = Ws[tx][k], w1 = Ws[tx + 16][k];
            a00 += h0 * w0; a01 += h0 * w1;
            a10 += h1 * w0; a11 += h1 * w1;
            a20 += h2 * w0; a21 += h2 * w1;
            a30 += h3 * w0; a31 += h3 * w1;
        }
        __syncthreads();
    }

    gs[ty     ][tx] = a00; gs[ty     ][tx + 16] = a01;
    gs[ty + 16][tx] = a10; gs[ty + 16][tx + 16] = a11;
    gs[ty + 32][tx] = a20; gs[ty + 32][tx + 16] = a21;
    gs[ty + 48][tx] = a30; gs[ty + 48][tx + 16] = a31;
    __syncthreads();

    for (int c = tid; c < 512; c += 256) {
        int b = c >> 3, hl = c & 7;
        int hg = hbase + hl;
        long long prow = ((long long)b * T + t) * 4096;
        float gi = gs[b][hl]      + pre[prow + hg];
        float gf = gs[b][8 + hl]  + pre[prow + 1024 + hg];
        float gg = gs[b][16 + hl] + pre[prow + 2048 + hg];
        float go = gs[b][24 + hl] + pre[prow + 3072 + hg];
        float si = 1.f / (1.f + __expf(-gi));
        float sf = 1.f / (1.f + __expf(-gf));
        float so = 1.f / (1.f + __expf(-go));
        float tg = tanhf(gg);
        int ci = b * 1024 + hg;
        float cn = sf * cstate[ci] + si * tg;
        float hn = so * tanhf(cn);
        cstate[ci] = cn;
        seq[((long long)b * T + t) * 1024 + hg] = hn;
    }
}

// ----------------------- softmax over 128 (rows = 4032) -----------------------
__global__ void softmax128(float* __restrict__ s) {
    int row = blockIdx.x;
    float* p = s + (long long)row * 128;
    int t = threadIdx.x;     // 128 threads
    __shared__ float red[4];
    float v = p[t];
    float m = v;
#pragma unroll
    for (int o = 16; o; o >>= 1) m = fmaxf(m, __shfl_xor_sync(0xffffffffu, m, o));
    if ((t & 31) == 0) red[t >> 5] = m;
    __syncthreads();
    m = fmaxf(fmaxf(red[0], red[1]), fmaxf(red[2], red[3]));
    __syncthreads();
    float e = __expf(v - m);
    float sum = e;
#pragma unroll
    for (int o = 16; o; o >>= 1) sum += __shfl_xor_sync(0xffffffffu, sum, o);
    if ((t & 31) == 0) red[t >> 5] = sum;
    __syncthreads();
    sum = red[0] + red[1] + red[2] + red[3];
    p[t] = e / sum;
}

// ----------------------- ctx = attn @ src_emb, written straight into d_out -----------------------
__global__ void __launch_bounds__(256) ctx_kernel(const float* __restrict__ attn,
                                                  const float* __restrict__ emb,
                                                  float* __restrict__ out) {
    int bt = blockIdx.x;                      // 0..4031
    int b = bt / 63, t = bt % 63;
    __shared__ float a[128];
    int tid = threadIdx.x;                    // 256
    if (tid < 128) a[tid] = attn[(long long)bt * 128 + tid];
    __syncthreads();
    const float* e = emb + (long long)b * 128 * 512;
    float acc0 = 0.f, acc1 = 0.f;
    int n0 = tid, n1 = tid + 256;
    for (int s = 0; s < 128; s++) {
        float av = a[s];
        acc0 += av * e[(long long)s * 512 + n0];
        acc1 += av * e[(long long)s * 512 + n1];
    }
    float* o = out + ((long long)b * 64 + (t + 1)) * 512;
    o[n0] = acc0;
    o[n1] = acc1;
}

// ----------------------- outputs[:,0,:]=0 and attn_weights copy -----------------------
__global__ void finalize(const float* __restrict__ attn, float* __restrict__ out) {
    int i = blockIdx.x * 256 + threadIdx.x;   // grid 128*256 = 32768
    if (i < 64 * 512) {
        int b = i >> 9, n = i & 511;
        out[((long long)b * 64) * 512 + n] = 0.f;
    }
    if (i < 64 * 128) {
        int b = i >> 7, s = i & 127;
        out[64LL * 64 * 512 + b * 128 + s] = attn[((long long)b * 63 + 62) * 128 + s];
    }
}

// ----------------------- host -----------------------
static float* addr_of(const void* symbol) {
    void* p = nullptr;
    cudaGetSymbolAddress(&p, symbol);
    return (float*)p;
}

extern "C" void kernel_launch(void* const* d_in, const int* in_sizes, int n_in,
                              void* d_out, int out_size) {
    const int*   src  = (const int*)d_in[0];
    const int*   trg  = (const int*)d_in[1];
    const float* srct = (const float*)d_in[2];
    const float* trgt = (const float*)d_in[3];
    const float* fcW  = (const float*)d_in[4];
    const float* fcb  = (const float*)d_in[5];
    const float* eW0  = (const float*)d_in[6];
    const float* eU0  = (const float*)d_in[7];
    const float* eb0  = (const float*)d_in[8];
    const float* ebb0 = (const float*)d_in[9];
    const float* eW1  = (const float*)d_in[10];
    const float* eU1  = (const float*)d_in[11];
    const float* eb1  = (const float*)d_in[12];
    const float* ebb1 = (const float*)d_in[13];
    const float* dW0  = (const float*)d_in[14];
    const float* dU0  = (const float*)d_in[15];
    const float* db0  = (const float*)d_in[16];
    const float* dbb0 = (const float*)d_in[17];
    const float* dW1  = (const float*)d_in[18];
    const float* dU1  = (const float*)d_in[19];
    const float* db1  = (const float*)d_in[20];
    const float* dbb1 = (const float*)d_in[21];
    float* out = (float*)d_out;

    float* srcemb = addr_of(g_srcemb);
    float* decemb = addr_of(g_decemb);
    float* pre    = addr_of(g_pre);
    float* seqA   = addr_of(g_seqA);
    float* seqB   = addr_of(g_seqB);
    float* dseqA  = addr_of(g_dseqA);
    float* dseqB  = addr_of(g_dseqB);
    float* preds  = addr_of(g_preds);
    float* scores = addr_of(g_scores);
    float* cst    = addr_of(g_cstate);
    float* zrow   = addr_of(g_zero);

    float* c0 = cst;
    float* c1 = cst + 64 * 1024;

    zero_init<<<512, 256>>>();
    gather_src<<<8192, 128>>>(src, srct, srcemb);

    // ---- encoder layer 0 ----
    gemm_abt<<<dim3(64, 64, 1), 256>>>(srcemb, eW0, eb0, ebb0, pre, 8192, 4096, 512, 1.f, 0, 0, 0);
    for (int t = 0; t < 128; t++) {
        const float* hp = t ? (seqA + (long long)(t - 1) * 1024) : zrow;
        long long hstr = t ? (long long)128 * 1024 : 0;
        lstm_step<<<128, 256>>>(pre, eU0, hp, hstr, c0, seqA, t, 128);
    }
    // ---- encoder layer 1 ----
    gemm_abt<<<dim3(64, 64, 1), 256>>>(seqA, eW1, eb1, ebb1, pre, 8192, 4096, 1024, 1.f, 0, 0, 0);
    for (int t = 0; t < 128; t++) {
        const float* hp = t ? (seqB + (long long)(t - 1) * 1024) : zrow;
        long long hstr = t ? (long long)128 * 1024 : 0;
        lstm_step<<<128, 256>>>(pre, eU1, hp, hstr, c1, seqB, t, 128);
    }

    gather_dec<<<4032, 128>>>(trg, trgt, decemb);

    // ---- decoder layer 0 (h,c continue from encoder layer 0 finals) ----
    gemm_abt<<<dim3(64, 32, 1), 256>>>(decemb, dW0, db0, dbb0, pre, 4032, 4096, 512, 1.f, 0, 0, 0);
    for (int t = 0; t < 63; t++) {
        const float* hp = t ? (dseqA + (long long)(t - 1) * 1024) : (seqA + (long long)127 * 1024);
        long long hstr = t ? (long long)63 * 1024 : (long long)128 * 1024;
        lstm_step<<<128, 256>>>(pre, dU0, hp, hstr, c0, dseqA, t, 63);
    }
    // ---- decoder layer 1 ----
    gemm_abt<<<dim3(64, 32, 1), 256>>>(dseqA, dW1, db1, dbb1, pre, 4032, 4096, 1024, 1.f, 0, 0, 0);
    for (int t = 0; t < 63; t++) {
        const float* hp = t ? (dseqB + (long long)(t - 1) * 1024) : (seqB + (long long)127 * 1024);
        long long hstr = t ? (long long)63 * 1024 : (long long)128 * 1024;
        lstm_step<<<128, 256>>>(pre, dU1, hp, hstr, c1, dseqB, t, 63);
    }

    // ---- fc ----
    gemm_abt<<<dim3(8, 32, 1), 256>>>(dseqB, fcW, fcb, nullptr, preds, 4032, 512, 1024, 1.f, 0, 0, 0);

    // ---- attention scores (batched over b): preds[b] @ src_emb[b]^T / SCALE ----
    float alpha = 1.f / sqrtf(512.f);
    gemm_abt<<<dim3(2, 1, 64), 256>>>(preds, srcemb, nullptr, nullptr, scores,
                                      63, 128, 512, alpha,
                                      (long long)63 * 512, (long long)128 * 512, (long long)63 * 128);
    softmax128<<<4032, 128>>>(scores);
    ctx_kernel<<<4032, 256>>>(scores, srcemb, out);
    finalize<<<128, 256>>>(scores, out);
}

// round 3
// speedup vs baseline: 1.6571x; 1.6571x over previous
#include <cuda_runtime.h>
#include <math.h>

// ----------------------- problem dims -----------------------
// B=64, S_SRC=128, T_TRG=64 -> TDEC=63, E=512, H=1024, 4H=4096, NL=2
// SOS=1, SCALE=sqrt(512)

typedef unsigned long long u64;

#define FMA2(acc, a, b) asm("fma.rn.f32x2 %0, %1, %2, %3;" : "=l"(acc) : "l"(a), "l"(b), "l"(acc))

__device__ __forceinline__ float psum(u64 v) {
    float lo, hi;
    asm("mov.b64 {%0,%1}, %2;" : "=f"(lo), "=f"(hi) : "l"(v));
    return lo + hi;
}

// ----------------------- device scratch (no allocation) -----------------------
__device__ float g_srcemb[8192 * 512];
__device__ float g_decemb[4032 * 512];
__device__ float g_pre[8192 * 4096];
__device__ float g_seqA[8192 * 1024];
__device__ float g_seqB[8192 * 1024];
__device__ float g_dseqA[4032 * 1024];
__device__ float g_dseqB[4032 * 1024];
__device__ float g_preds[4032 * 512];
__device__ float g_scores[4032 * 128];
__device__ float g_cstate[2 * 64 * 1024];
__device__ float g_zero[1024];

// ----------------------- init -----------------------
__global__ void zero_init() {
    int i = blockIdx.x * 256 + threadIdx.x;
    if (i < 2 * 64 * 1024) g_cstate[i] = 0.f;
    if (i < 1024) g_zero[i] = 0.f;
}

// ----------------------- embedding gathers -----------------------
__global__ void gather_src(const int* __restrict__ src, const float* __restrict__ tab,
                           float* __restrict__ out) {
    int row = blockIdx.x;
    int tok = src[row];
    const float4* r = (const float4*)(tab + (long long)tok * 512);
    float4* o = (float4*)(out + (long long)row * 512);
    o[threadIdx.x] = r[threadIdx.x];
}

__global__ void gather_dec(const int* __restrict__ trg, const float* __restrict__ tab,
                           float* __restrict__ out) {
    int row = blockIdx.x;
    int b = row / 63, t = row % 63;
    int tok = (t == 0) ? 1 : trg[b * 64 + t];
    const float4* r = (const float4*)(tab + (long long)tok * 512);
    float4* o = (float4*)(out + (long long)row * 512);
    o[threadIdx.x] = r[threadIdx.x];
}

// ----------------------- C = alpha*(A @ W^T) + b1 + b2 (f32x2, pipelined) -----------------------
// A:[M,K] rm, W:[N,K] rm, C:[M,N]. Block tile 128x64, BK=32, 256 thr, 8x4 microtile.
// Accumulators packed over k-parity in u64 (fma.rn.f32x2). K multiple of 32.
__global__ void __launch_bounds__(256, 1) gemm_abt(
    const float* __restrict__ A, const float* __restrict__ W,
    const float* __restrict__ b1, const float* __restrict__ b2,
    float* __restrict__ C,
    int M, int N, int K, float alpha,
    long long strideA, long long strideW, long long strideC)
{
    A += (long long)blockIdx.z * strideA;
    W += (long long)blockIdx.z * strideW;
    C += (long long)blockIdx.z * strideC;

    __shared__ __align__(16) float As[2][128][36];
    __shared__ __align__(16) float Bs[2][64][36];

    int tid = threadIdx.x;
    int m0 = blockIdx.y * 128;
    int n0 = blockIdx.x * 64;
    int ty = tid >> 4, tx = tid & 15;

    u64 acc[8][4];
#pragma unroll
    for (int i = 0; i < 8; i++)
#pragma unroll
        for (int j = 0; j < 4; j++) acc[i][j] = 0ull;

    // staging registers
    float4 sa[4], sb[2];
    const float4 z4 = {0.f, 0.f, 0.f, 0.f};

    int nch = K >> 5;

    // ---- prologue: load chunk 0 ----
#pragma unroll
    for (int r = 0; r < 4; r++) {
        int li = tid + r * 256;
        int m = li >> 3, kq = li & 7;
        sa[r] = (m0 + m < M) ? *(const float4*)&A[(long long)(m0 + m) * K + kq * 4] : z4;
    }
#pragma unroll
    for (int r = 0; r < 2; r++) {
        int li = tid + r * 256;
        int n = li >> 3, kq = li & 7;
        sb[r] = *(const float4*)&W[(long long)(n0 + n) * K + kq * 4];
    }
#pragma unroll
    for (int r = 0; r < 4; r++) {
        int li = tid + r * 256;
        int m = li >> 3, kq = li & 7;
        *(float4*)&As[0][m][kq * 4] = sa[r];
    }
#pragma unroll
    for (int r = 0; r < 2; r++) {
        int li = tid + r * 256;
        int n = li >> 3, kq = li & 7;
        *(float4*)&Bs[0][n][kq * 4] = sb[r];
    }
    __syncthreads();

    for (int c = 0; c < nch; c++) {
        int cur = c & 1;
        int kc = (c + 1) << 5;
        if (c + 1 < nch) {
#pragma unroll
            for (int r = 0; r < 4; r++) {
                int li = tid + r * 256;
                int m = li >> 3, kq = li & 7;
                sa[r] = (m0 + m < M) ? *(const float4*)&A[(long long)(m0 + m) * K + kc + kq * 4] : z4;
            }
#pragma unroll
            for (int r = 0; r < 2; r++) {
                int li = tid + r * 256;
                int n = li >> 3, kq = li & 7;
                sb[r] = *(const float4*)&W[(long long)(n0 + n) * K + kc + kq * 4];
            }
        }

#pragma unroll
        for (int q = 0; q < 8; q++) {
            int k = q * 4;
            ulonglong2 a[8], w[4];
#pragma unroll
            for (int i = 0; i < 8; i++) a[i] = *(const ulonglong2*)&As[cur][ty + 16 * i][k];
#pragma unroll
            for (int j = 0; j < 4; j++) w[j] = *(const ulonglong2*)&Bs[cur][tx + 16 * j][k];
#pragma unroll
            for (int i = 0; i < 8; i++)
#pragma unroll
                for (int j = 0; j < 4; j++) {
                    FMA2(acc[i][j], a[i].x, w[j].x);
                    FMA2(acc[i][j], a[i].y, w[j].y);
                }
        }

        if (c + 1 < nch) {
            int nb = cur ^ 1;
#pragma unroll
            for (int r = 0; r < 4; r++) {
                int li = tid + r * 256;
                int m = li >> 3, kq = li & 7;
                *(float4*)&As[nb][m][kq * 4] = sa[r];
            }
#pragma unroll
            for (int r = 0; r < 2; r++) {
                int li = tid + r * 256;
                int n = li >> 3, kq = li & 7;
                *(float4*)&Bs[nb][n][kq * 4] = sb[r];
            }
        }
        __syncthreads();
    }

#pragma unroll
    for (int i = 0; i < 8; i++) {
        int m = m0 + ty + 16 * i;
        if (m >= M) continue;
#pragma unroll
        for (int j = 0; j < 4; j++) {
            int n = n0 + tx + 16 * j;
            float v = psum(acc[i][j]) * alpha;
            if (b1) v += b1[n];
            if (b2) v += b2[n];
            C[(long long)m * N + n] = v;
        }
    }
}

// ----------------------- fused LSTM timestep (f32x2, pipelined) -----------------------
// Block bx owns h-indices [bx*8, bx*8+8) x 4 gates (32 Whh rows), all 64 batches.
// gates = pre[t] + hprev @ Whh^T; epilogue applies the LSTM cell.
__global__ void __launch_bounds__(256, 1) lstm_step(
    const float* __restrict__ pre,
    const float* __restrict__ Whh,
    const float* __restrict__ hprev, long long hbstride,
    float* __restrict__ cstate,
    float* __restrict__ seq,
    int t, int T)
{
    __shared__ __align__(16) float Hs[2][64][36];
    __shared__ __align__(16) float Ws[2][32][36];
    __shared__ float gs[64][33];

    int tid = threadIdx.x;
    int hbase = blockIdx.x * 8;
    int ty = tid >> 4, tx = tid & 15;

    u64 acc[4][2];
#pragma unroll
    for (int i = 0; i < 4; i++) { acc[i][0] = 0ull; acc[i][1] = 0ull; }

    float4 sh[2], sw;

    // row mapping for W loads: 32 rows = gate g (0..3) x h-lane (0..7)
    // prologue chunk 0
#pragma unroll
    for (int r = 0; r < 2; r++) {
        int li = tid + r * 256;
        int b = li >> 3, kq = li & 7;
        sh[r] = *(const float4*)&hprev[(long long)b * hbstride + kq * 4];
    }
    {
        int rr = tid >> 3, kq = tid & 7;
        int grow = (rr >> 3) * 1024 + hbase + (rr & 7);
        sw = *(const float4*)&Whh[(long long)grow * 1024 + kq * 4];
    }
#pragma unroll
    for (int r = 0; r < 2; r++) {
        int li = tid + r * 256;
        int b = li >> 3, kq = li & 7;
        *(float4*)&Hs[0][b][kq * 4] = sh[r];
    }
    {
        int rr = tid >> 3, kq = tid & 7;
        *(float4*)&Ws[0][rr][kq * 4] = sw;
    }
    __syncthreads();

    for (int c = 0; c < 32; c++) {
        int cur = c & 1;
        int kc = (c + 1) << 5;
        if (c + 1 < 32) {
#pragma unroll
            for (int r = 0; r < 2; r++) {
                int li = tid + r * 256;
                int b = li >> 3, kq = li & 7;
                sh[r] = *(const float4*)&hprev[(long long)b * hbstride + kc + kq * 4];
            }
            {
                int rr = tid >> 3, kq = tid & 7;
                int grow = (rr >> 3) * 1024 + hbase + (rr & 7);
                sw = *(const float4*)&Whh[(long long)grow * 1024 + kc + kq * 4];
            }
        }

#pragma unroll
        for (int q = 0; q < 8; q++) {
            int k = q * 4;
            ulonglong2 h0 = *(const ulonglong2*)&Hs[cur][ty][k];
            ulonglong2 h1 = *(const ulonglong2*)&Hs[cur][ty + 16][k];
            ulonglong2 h2 = *(const ulonglong2*)&Hs[cur][ty + 32][k];
            ulonglong2 h3 = *(const ulonglong2*)&Hs[cur][ty + 48][k];
            ulonglong2 w0 = *(const ulonglong2*)&Ws[cur][tx][k];
            ulonglong2 w1 = *(const ulonglong2*)&Ws[cur][tx + 16][k];
            FMA2(acc[0][0], h0.x, w0.x); FMA2(acc[0][0], h0.y, w0.y);
            FMA2(acc[0][1], h0.x, w1.x); FMA2(acc[0][1], h0.y, w1.y);
            FMA2(acc[1][0], h1.x, w0.x); FMA2(acc[1][0], h1.y, w0.y);
            FMA2(acc[1][1], h1.x, w1.x); FMA2(acc[1][1], h1.y, w1.y);
            FMA2(acc[2][0], h2.x, w0.x); FMA2(acc[2][0], h2.y, w0.y);
            FMA2(acc[2][1], h2.x, w1.x); FMA2(acc[2][1], h2.y, w1.y);
            FMA2(acc[3][0], h3.x, w0.x); FMA2(acc[3][0], h3.y, w0.y);
            FMA2(acc[3][1], h3.x, w1.x); FMA2(acc[3][1], h3.y, w1.y);
        }

        if (c + 1 < 32) {
            int nb = cur ^ 1;
#pragma unroll
            for (int r = 0; r < 2; r++) {
                int li = tid + r * 256;
                int b = li >> 3, kq = li & 7;
                *(float4*)&Hs[nb][b][kq * 4] = sh[r];
            }
            {
                int rr = tid >> 3, kq = tid & 7;
                *(float4*)&Ws[nb][rr][kq * 4] = sw;
            }
        }
        __syncthreads();
    }

#pragma unroll
    for (int i = 0; i < 4; i++) {
        gs[ty + 16 * i][tx]      = psum(acc[i][0]);
        gs[ty + 16 * i][tx + 16] = psum(acc[i][1]);
    }
    __syncthreads();

    for (int cidx = tid; cidx < 512; cidx += 256) {
        int b = cidx >> 3, hl = cidx & 7;
        int hg = hbase + hl;
        long long prow = ((long long)b * T + t) * 4096;
        float gi = gs[b][hl]      + pre[prow + hg];
        float gf = gs[b][8 + hl]  + pre[prow + 1024 + hg];
        float gg = gs[b][16 + hl] + pre[prow + 2048 + hg];
        float go = gs[b][24 + hl] + pre[prow + 3072 + hg];
        float si = 1.f / (1.f + __expf(-gi));
        float sf = 1.f / (1.f + __expf(-gf));
        float so = 1.f / (1.f + __expf(-go));
        float tg = tanhf(gg);
        int ci = b * 1024 + hg;
        float cn = sf * cstate[ci] + si * tg;
        float hn = so * tanhf(cn);
        cstate[ci] = cn;
        seq[((long long)b * T + t) * 1024 + hg] = hn;
    }
}

// ----------------------- softmax over 128 (rows = 4032) -----------------------
__global__ void softmax128(float* __restrict__ s) {
    int row = blockIdx.x;
    float* p = s + (long long)row * 128;
    int t = threadIdx.x;
    __shared__ float red[4];
    float v = p[t];
    float m = v;
#pragma unroll
    for (int o = 16; o; o >>= 1) m = fmaxf(m, __shfl_xor_sync(0xffffffffu, m, o));
    if ((t & 31) == 0) red[t >> 5] = m;
    __syncthreads();
    m = fmaxf(fmaxf(red[0], red[1]), fmaxf(red[2], red[3]));
    __syncthreads();
    float e = __expf(v - m);
    float sum = e;
#pragma unroll
    for (int o = 16; o; o >>= 1) sum += __shfl_xor_sync(0xffffffffu, sum, o);
    if ((t & 31) == 0) red[t >> 5] = sum;
    __syncthreads();
    sum = red[0] + red[1] + red[2] + red[3];
    p[t] = e / sum;
}

// ----------------------- ctx = attn @ src_emb -> d_out -----------------------
__global__ void __launch_bounds__(256) ctx_kernel(const float* __restrict__ attn,
                                                  const float* __restrict__ emb,
                                                  float* __restrict__ out) {
    int bt = blockIdx.x;
    int b = bt / 63, t = bt % 63;
    __shared__ float a[128];
    int tid = threadIdx.x;
    if (tid < 128) a[tid] = attn[(long long)bt * 128 + tid];
    __syncthreads();
    const float* e = emb + (long long)b * 128 * 512;
    float acc0 = 0.f, acc1 = 0.f;
    int n0 = tid, n1 = tid + 256;
    for (int s = 0; s < 128; s++) {
        float av = a[s];
        acc0 += av * e[(long long)s * 512 + n0];
        acc1 += av * e[(long long)s * 512 + n1];
    }
    float* o = out + ((long long)b * 64 + (t + 1)) * 512;
    o[n0] = acc0;
    o[n1] = acc1;
}

// ----------------------- outputs[:,0,:]=0 and attn_weights copy -----------------------
__global__ void finalize(const float* __restrict__ attn, float* __restrict__ out) {
    int i = blockIdx.x * 256 + threadIdx.x;
    if (i < 64 * 512) {
        int b = i >> 9, n = i & 511;
        out[((long long)b * 64) * 512 + n] = 0.f;
    }
    if (i < 64 * 128) {
        int b = i >> 7, s = i & 127;
        out[64LL * 64 * 512 + b * 128 + s] = attn[((long long)b * 63 + 62) * 128 + s];
    }
}

// ----------------------- host -----------------------
static float* addr_of(const void* symbol) {
    void* p = nullptr;
    cudaGetSymbolAddress(&p, symbol);
    return (float*)p;
}

extern "C" void kernel_launch(void* const* d_in, const int* in_sizes, int n_in,
                              void* d_out, int out_size) {
    const int*   src  = (const int*)d_in[0];
    const int*   trg  = (const int*)d_in[1];
    const float* srct = (const float*)d_in[2];
    const float* trgt = (const float*)d_in[3];
    const float* fcW  = (const float*)d_in[4];
    const float* fcb  = (const float*)d_in[5];
    const float* eW0  = (const float*)d_in[6];
    const float* eU0  = (const float*)d_in[7];
    const float* eb0  = (const float*)d_in[8];
    const float* ebb0 = (const float*)d_in[9];
    const float* eW1  = (const float*)d_in[10];
    const float* eU1  = (const float*)d_in[11];
    const float* eb1  = (const float*)d_in[12];
    const float* ebb1 = (const float*)d_in[13];
    const float* dW0  = (const float*)d_in[14];
    const float* dU0  = (const float*)d_in[15];
    const float* db0  = (const float*)d_in[16];
    const float* dbb0 = (const float*)d_in[17];
    const float* dW1  = (const float*)d_in[18];
    const float* dU1  = (const float*)d_in[19];
    const float* db1  = (const float*)d_in[20];
    const float* dbb1 = (const float*)d_in[21];
    float* out = (float*)d_out;

    float* srcemb = addr_of(g_srcemb);
    float* decemb = addr_of(g_decemb);
    float* pre    = addr_of(g_pre);
    float* seqA   = addr_of(g_seqA);
    float* seqB   = addr_of(g_seqB);
    float* dseqA  = addr_of(g_dseqA);
    float* dseqB  = addr_of(g_dseqB);
    float* preds  = addr_of(g_preds);
    float* scores = addr_of(g_scores);
    float* cst    = addr_of(g_cstate);
    float* zrow   = addr_of(g_zero);

    float* c0 = cst;
    float* c1 = cst + 64 * 1024;

    zero_init<<<512, 256>>>();
    gather_src<<<8192, 128>>>(src, srct, srcemb);

    // ---- encoder layer 0 ----
    gemm_abt<<<dim3(64, 64, 1), 256>>>(srcemb, eW0, eb0, ebb0, pre, 8192, 4096, 512, 1.f, 0, 0, 0);
    for (int t = 0; t < 128; t++) {
        const float* hp = t ? (seqA + (long long)(t - 1) * 1024) : zrow;
        long long hstr = t ? (long long)128 * 1024 : 0;
        lstm_step<<<128, 256>>>(pre, eU0, hp, hstr, c0, seqA, t, 128);
    }
    // ---- encoder layer 1 ----
    gemm_abt<<<dim3(64, 64, 1), 256>>>(seqA, eW1, eb1, ebb1, pre, 8192, 4096, 1024, 1.f, 0, 0, 0);
    for (int t = 0; t < 128; t++) {
        const float* hp = t ? (seqB + (long long)(t - 1) * 1024) : zrow;
        long long hstr = t ? (long long)128 * 1024 : 0;
        lstm_step<<<128, 256>>>(pre, eU1, hp, hstr, c1, seqB, t, 128);
    }

    gather_dec<<<4032, 128>>>(trg, trgt, decemb);

    // ---- decoder layer 0 ----
    gemm_abt<<<dim3(64, 32, 1), 256>>>(decemb, dW0, db0, dbb0, pre, 4032, 4096, 512, 1.f, 0, 0, 0);
    for (int t = 0; t < 63; t++) {
        const float* hp = t ? (dseqA + (long long)(t - 1) * 1024) : (seqA + (long long)127 * 1024);
        long long hstr = t ? (long long)63 * 1024 : (long long)128 * 1024;
        lstm_step<<<128, 256>>>(pre, dU0, hp, hstr, c0, dseqA, t, 63);
    }
    // ---- decoder layer 1 ----
    gemm_abt<<<dim3(64, 32, 1), 256>>>(dseqA, dW1, db1, dbb1, pre, 4032, 4096, 1024, 1.f, 0, 0, 0);
    for (int t = 0; t < 63; t++) {
        const float* hp = t ? (dseqB + (long long)(t - 1) * 1024) : (seqB + (long long)127 * 1024);
        long long hstr = t ? (long long)63 * 1024 : (long long)128 * 1024;
        lstm_step<<<128, 256>>>(pre, dU1, hp, hstr, c1, dseqB, t, 63);
    }

    // ---- fc ----
    gemm_abt<<<dim3(8, 32, 1), 256>>>(dseqB, fcW, fcb, nullptr, preds, 4032, 512, 1024, 1.f, 0, 0, 0);

    // ---- attention scores: preds[b] @ src_emb[b]^T / SCALE ----
    float alpha = 1.f / sqrtf(512.f);
    gemm_abt<<<dim3(2, 1, 64), 256>>>(preds, srcemb, nullptr, nullptr, scores,
                                      63, 128, 512, alpha,
                                      (long long)63 * 512, (long long)128 * 512, (long long)63 * 128);
    softmax128<<<4032, 128>>>(scores);
    ctx_kernel<<<4032, 256>>>(scores, srcemb, out);
    finalize<<<128, 256>>>(scores, out);
}